// round 16
// baseline (speedup 1.0000x reference)
#include <cuda_runtime.h>
#include <math.h>

#define L2L   2
#define HID   512
#define TMAX  20
#define VOC   10000
#define BATCH 32
#define SPOS  49
#define VPAD  10112   // 632 tiles * 16 cols
#define NB    148
#define NT    256
#define GW    (NB*8)  // 1184 global warps
typedef unsigned long long ull;

// ---------------- weights in k-pair layout: W2[kp][n] = (W[n][2kp], W[n][2kp+1]) ----------------
__device__ __align__(16) float2 g_Wih2[L2L][HID/2][4*HID];
__device__ __align__(16) float2 g_Whh2[L2L][HID/2][4*HID];
__device__ __align__(16) float2 g_Wq2[HID/2][HID];
__device__ __align__(16) float2 g_hattW2[HID][HID];      // k=1024 -> 512 kp rows
__device__ __align__(16) float2 g_projW2[HID/2][VPAD];
// ---------------- activations in kp-transposed layout: XT[kp][row] = (x[row][2kp], x[row][2kp+1]) ----------------
__device__ ull g_embT [HID/2][BATCH];
__device__ ull g_h0T  [HID/2][BATCH];
__device__ ull g_h1T  [HID/2][BATCH];
__device__ ull g_hcatT[HID/2][2*BATCH];   // cols: [l0 b0..31 | l1 b0..31]
__device__ ull g_attnT[HID/2][2*BATCH];
__device__ float g_keys[BATCH][SPOS][HID];
__device__ float g_vals[BATCH][SPOS][HID];
__device__ float g_c[L2L*BATCH*HID];
__device__ float g_Pg[8][BATCH][4*HID];
__device__ float g_Pp[8][BATCH][VPAD];
__device__ float g_Pq[8][2*BATCH][HID];
__device__ float g_Ph[16][2*BATCH][HID];
__device__ float g_tmp[TMAX][BATCH][VOC];
__device__ float g_amv[BATCH][40];
__device__ int   g_ami[BATCH][40];
__device__ unsigned g_bar;

__device__ __forceinline__ void fma2(ull &a, ull x, ull w){
    asm("fma.rn.f32x2 %0, %1, %2, %0;" : "+l"(a) : "l"(x), "l"(w));
}

// ---------------- grid-wide barrier ----------------
__device__ __forceinline__ void gridbar(){
    __syncthreads();
    if (threadIdx.x == 0){
        __threadfence();
        unsigned ret = atomicAdd(&g_bar, 1u);
        unsigned gen = ret >> 16;
        if ((ret & 0xFFFFu) == NB - 1u){
            atomicAdd(&g_bar, 0x10000u - NB);
        } else {
            while (((*(volatile unsigned*)&g_bar) >> 16) == gen){ }
        }
        __threadfence();
    }
    __syncthreads();
}

// ---------------- GEMM warp-unit: lane=row, thread covers 16 cols, KP k-pairs ----------------
// Pout must be P + row*N.  XT pre-offset to slice kp start (row stride NR ull).
__device__ __forceinline__ void gunit(const ull* __restrict__ XT, int NR, int row,
        const float2* __restrict__ W2, int N, int KP,
        float* __restrict__ Pout, int n0){
    ull acc[16];
    #pragma unroll
    for (int i = 0; i < 16; i++) acc[i] = 0ULL;
    const ull* xp = XT + row;
    const float2* wp = W2 + n0;
    #pragma unroll 2
    for (int kp = 0; kp < KP; kp++){
        ull x2 = xp[(size_t)kp * NR];
        const ulonglong2* w4 = reinterpret_cast<const ulonglong2*>(wp + (size_t)kp * N);
        #pragma unroll
        for (int i = 0; i < 8; i++){
            ulonglong2 wv = w4[i];
            fma2(acc[2*i],   x2, wv.x);
            fma2(acc[2*i+1], x2, wv.y);
        }
    }
    #pragma unroll
    for (int i = 0; i < 4; i++){
        float2 a = *reinterpret_cast<float2*>(&acc[4*i+0]);
        float2 b = *reinterpret_cast<float2*>(&acc[4*i+1]);
        float2 c = *reinterpret_cast<float2*>(&acc[4*i+2]);
        float2 d = *reinterpret_cast<float2*>(&acc[4*i+3]);
        float4 o; o.x = a.x+a.y; o.y = b.x+b.y; o.z = c.x+c.y; o.w = d.x+d.y;
        *reinterpret_cast<float4*>(Pout + n0 + 4*i) = o;
    }
}

// ---------------- phases ----------------
__device__ __forceinline__ void phase_lstm_gemm(int l, const ull* xT, const ull* hT,
                                                int wu0, int lane){
    for (int v = wu0; v < 1024; v += GW){
        int ct = v & 127, s = v >> 7;              // 8 slices, KC=128 (64 kp)
        const ull* src = (s < 4) ? xT : hT;
        int kpo = (s & 3) * 64;
        const float2* W2 = (s < 4 ? &g_Wih2[l][0][0] : &g_Whh2[l][0][0]) + (size_t)kpo * (4*HID);
        gunit(src + (size_t)kpo * 32, 32, lane, W2, 4*HID, 64,
              &g_Pg[s][0][0] + (size_t)lane * (4*HID), ct * 16);
    }
}

__device__ __forceinline__ void phase_lstm_act(int l, const float* bih, const float* bhh,
                                               int wu0, int lane){
    for (int v = wu0; v < 512; v += GW){
        int b = v >> 4, j = (v & 15) * 32 + lane;
        int bo = l * 4 * HID;
        float gi = bih[bo + j]         + bhh[bo + j];
        float gf = bih[bo + HID + j]   + bhh[bo + HID + j];
        float gg = bih[bo + 2*HID + j] + bhh[bo + 2*HID + j];
        float go = bih[bo + 3*HID + j] + bhh[bo + 3*HID + j];
        #pragma unroll
        for (int s = 0; s < 8; s++){
            const float* p = &g_Pg[s][b][0];
            gi += p[j]; gf += p[HID + j]; gg += p[2*HID + j]; go += p[3*HID + j];
        }
        int idx = (l * BATCH + b) * HID + j;
        float cold = g_c[idx];
        float si = 1.f / (1.f + expf(-gi));
        float sf = 1.f / (1.f + expf(-gf));
        float so = 1.f / (1.f + expf(-go));
        float c2 = sf * cold + si * tanhf(gg);
        g_c[idx] = c2;
        float h = so * tanhf(c2);
        float* hT = (float*)(l == 0 ? &g_h0T[0][0] : &g_h1T[0][0]);
        hT[(((j >> 1) * 32) + b) * 2 + (j & 1)] = h;
        ((float*)&g_hcatT[0][0])[(((j >> 1) * 64) + l*32 + b) * 2 + (j & 1)] = h;
    }
}

__device__ __forceinline__ void phase_projq(const ull* xT, int withQ, int wu0, int lane){
    for (int v = wu0; v < 5568; v += GW){
        if (v < 5056){
            int ct = v % 632, s = v / 632;         // 8 slices, KC=64 (32 kp)
            gunit(xT + (size_t)(s*32) * 32, 32, lane,
                  &g_projW2[0][0] + (size_t)(s*32) * VPAD, VPAD, 32,
                  &g_Pp[s][0][0] + (size_t)lane * VPAD, ct * 16);
        } else if (withQ){
            int w = v - 5056;
            int ct = w & 31, s = (w >> 5) & 7, rg = w >> 8;
            int row = rg * 32 + lane;
            gunit(&g_hcatT[0][0] + (size_t)(s*32) * 64, 64, row,
                  &g_Wq2[0][0] + (size_t)(s*32) * HID, HID, 32,
                  &g_Pq[s][0][0] + (size_t)row * HID, ct * 16);
        }
    }
}

__device__ __forceinline__ void attention_warp(int aw, const float* bq, int lane){
    int lb = aw & 63, half = aw >> 6;
    int b = lb & 31;
    float qv[16];
    #pragma unroll
    for (int i = 0; i < 16; i++){
        int j = i*32 + lane;
        float a = bq[j];
        #pragma unroll
        for (int s = 0; s < 8; s++) a += g_Pq[s][lb][j];
        qv[i] = tanhf(a);
    }
    float scA = 0.f, scB = -INFINITY;
    for (int s = 0; s < SPOS; s++){
        const float* kp = &g_keys[b][s][0];
        float d = 0.f;
        #pragma unroll
        for (int i = 0; i < 16; i++) d += qv[i] * __ldg(kp + i*32 + lane);
        #pragma unroll
        for (int o = 16; o > 0; o >>= 1) d += __shfl_xor_sync(0xffffffffu, d, o);
        d *= (1.f / 7.f);
        if (lane == s)      scA = d;
        if (lane + 32 == s) scB = d;
    }
    float m = fmaxf(scA, scB);
    #pragma unroll
    for (int o = 16; o > 0; o >>= 1) m = fmaxf(m, __shfl_xor_sync(0xffffffffu, m, o));
    float eA = expf(scA - m);
    float eB = (lane + 32 < SPOS) ? expf(scB - m) : 0.f;
    float ssum = eA + eB;
    #pragma unroll
    for (int o = 16; o > 0; o >>= 1) ssum += __shfl_xor_sync(0xffffffffu, ssum, o);
    float inv = 1.f / ssum;
    float wA = eA * inv, wB = eB * inv;
    float av[8];
    #pragma unroll
    for (int i = 0; i < 8; i++) av[i] = 0.f;
    for (int s = 0; s < SPOS; s++){
        float w = (s < 32) ? __shfl_sync(0xffffffffu, wA, s)
                           : __shfl_sync(0xffffffffu, wB, s - 32);
        const float* vp = &g_vals[b][s][0];
        #pragma unroll
        for (int i = 0; i < 8; i++) av[i] += w * __ldg(vp + (half*8 + i)*32 + lane);
    }
    #pragma unroll
    for (int i = 0; i < 8; i++){
        float partner = __shfl_down_sync(0xffffffffu, av[i], 1);
        if ((lane & 1) == 0){
            int kpair = (half*8 + i)*16 + (lane >> 1);
            ull u; asm("mov.b64 %0, {%1, %2};" : "=l"(u) : "f"(av[i]), "f"(partner));
            g_attnT[kpair][lb] = u;
        }
    }
}

__device__ __forceinline__ void phase_logits_attn(int tslot, int withAttn,
        const float* projb, const float* bq, int wu0, int lane){
    for (int v = wu0; v < GW; v += GW){
        if (v < 1056){
            int b = v / 33, ch = v % 33;
            int vend = ch*304 + 304; if (vend > VOC) vend = VOC;
            float best = -INFINITY; int bi = 0;
            for (int vi = ch*304 + lane; vi < vend; vi += 32){
                float val = projb[vi];
                #pragma unroll
                for (int s = 0; s < 8; s++) val += g_Pp[s][b][vi];
                g_tmp[tslot][b][vi] = val;
                if (val > best){ best = val; bi = vi; }
            }
            #pragma unroll
            for (int o = 16; o > 0; o >>= 1){
                float ov = __shfl_xor_sync(0xffffffffu, best, o);
                int   oi = __shfl_xor_sync(0xffffffffu, bi, o);
                if (ov > best || (ov == best && oi < bi)){ best = ov; bi = oi; }
            }
            if (lane == 0){ g_amv[b][ch] = best; g_ami[b][ch] = bi; }
        } else if (withAttn){
            attention_warp(v - 1056, bq, lane);
        }
    }
}

__device__ __forceinline__ void phase_amhatt(const float* embed, int wu0, int lane){
    for (int v = wu0; v < 1056; v += GW){
        if (v < 32){
            int b = v;
            float best = g_amv[b][0]; int bi = g_ami[b][0];
            for (int ch = 1; ch < 33; ch++){
                float vv = g_amv[b][ch]; int ii = g_ami[b][ch];
                if (vv > best || (vv == best && ii < bi)){ best = vv; bi = ii; }
            }
            const float4* e4 = reinterpret_cast<const float4*>(embed + (size_t)bi * HID);
            #pragma unroll
            for (int q = 0; q < 4; q++){
                float4 e = __ldg(&e4[lane*4 + q]);
                int kp0 = lane*8 + q*2;
                ull u0, u1;
                asm("mov.b64 %0, {%1, %2};" : "=l"(u0) : "f"(e.x), "f"(e.y));
                asm("mov.b64 %0, {%1, %2};" : "=l"(u1) : "f"(e.z), "f"(e.w));
                g_embT[kp0][b] = u0; g_embT[kp0+1][b] = u1;
            }
        } else {
            int w = v - 32;
            int ct = w & 31, s = (w >> 5) & 15, rg = w >> 9;   // 16 slices KC=64
            int row = rg * 32 + lane;
            const ull* src = (s < 8) ? &g_attnT[0][0] : &g_hcatT[0][0];
            int kpo = (s & 7) * 32;
            int wrow = (s < 8 ? 0 : 256) + kpo;
            gunit(src + (size_t)kpo * 64, 64, row,
                  &g_hattW2[0][0] + (size_t)wrow * HID, HID, 32,
                  &g_Ph[s][0][0] + (size_t)row * HID, ct * 16);
        }
    }
}

__device__ __forceinline__ void phase_hatt_act(const float* hattb, int wu0, int lane){
    for (int v = wu0; v < 1024; v += GW){
        int lb = v >> 4, j = (v & 15) * 32 + lane;
        float a = hattb[j];
        #pragma unroll
        for (int s = 0; s < 16; s++) a += g_Ph[s][lb][j];
        float h = tanhf(a);
        float* hT = (float*)(lb < 32 ? &g_h0T[0][0] : &g_h1T[0][0]);
        int b = lb & 31;
        hT[(((j >> 1) * 32) + b) * 2 + (j & 1)] = h;
        ((float*)&g_hcatT[0][0])[(((j >> 1) * 64) + lb) * 2 + (j & 1)] = h;
    }
}

__device__ __forceinline__ void phase_out(float* out, int wu0, int lane){
    for (int wu = wu0; wu < 10000; wu += GW){
        int e = wu*32 + lane;
        int b = e / VOC, v = e % VOC;
        float r[TMAX];
        #pragma unroll
        for (int t = 0; t < TMAX; t++) r[t] = g_tmp[t][b][v];
        float4* o4 = reinterpret_cast<float4*>(out + ((size_t)b*VOC + v)*TMAX);
        #pragma unroll
        for (int i = 0; i < 5; i++) o4[i] = reinterpret_cast<float4*>(r)[i];
    }
}

// ---------------- persistent decoder ----------------
__global__ __launch_bounds__(NT, 1)
void decoder_persistent(const float* __restrict__ bq, const float* __restrict__ bih,
                        const float* __restrict__ bhh, const float* __restrict__ projb,
                        const float* __restrict__ hattb, const float* __restrict__ embed,
                        float* __restrict__ out){
    int wu0 = (threadIdx.x >> 5) * NB + blockIdx.x;
    int lane = threadIdx.x & 31;

    phase_projq(&g_embT[0][0], 0, wu0, lane);
    gridbar();
    phase_logits_attn(0, 0, projb, bq, wu0, lane);
    gridbar();

    for (int t = 0; t < TMAX - 1; t++){
        phase_lstm_gemm(0, &g_embT[0][0], &g_h0T[0][0], wu0, lane);
        gridbar();
        phase_lstm_act(0, bih, bhh, wu0, lane);
        gridbar();
        phase_lstm_gemm(1, &g_h0T[0][0], &g_h1T[0][0], wu0, lane);
        gridbar();
        phase_lstm_act(1, bih, bhh, wu0, lane);
        gridbar();
        int more = (t < TMAX - 2);
        phase_projq(&g_h1T[0][0], more, wu0, lane);
        gridbar();
        phase_logits_attn(t + 1, more, projb, bq, wu0, lane);
        gridbar();
        if (more){
            phase_amhatt(embed, wu0, lane);
            gridbar();
            phase_hatt_act(hattb, wu0, lane);
            gridbar();
        }
    }
    phase_out(out, wu0, lane);
}

// ---------------- setup: k-pair transpose  W2[kp][n] = (W[n][2kp], W[n][2kp+1]) ----------------
__global__ void transpose_pair(const float* __restrict__ W, float2* __restrict__ W2,
                               int N, int K, int Npad){
    __shared__ float t[32][33];
    int n0 = blockIdx.x * 32, k0 = blockIdx.y * 32;
    int tx = threadIdx.x, ty = threadIdx.y;   // 32 x 8
    #pragma unroll
    for (int r = 0; r < 4; r++){
        int n = n0 + ty + r*8, k = k0 + tx;
        t[ty + r*8][tx] = (n < N && k < K) ? W[(size_t)n * K + k] : 0.f;
    }
    __syncthreads();
    #pragma unroll
    for (int r = 0; r < 2; r++){
        int kpl = ty + r*8;
        float2 v; v.x = t[tx][2*kpl]; v.y = t[tx][2*kpl + 1];
        W2[(size_t)(k0/2 + kpl) * Npad + n0 + tx] = v;
    }
}

__global__ void precompute_kv(const float* __restrict__ img, const float* __restrict__ Wk,
                              const float* __restrict__ bk, const float* __restrict__ Wv,
                              const float* __restrict__ bv){
    __shared__ float wk_s[SPOS][SPOS], wv_s[SPOS][SPOS];
    __shared__ float bk_s[SPOS], bv_s[SPOS];
    int tid = threadIdx.x;
    for (int i = tid; i < SPOS*SPOS; i += 128){ wk_s[i/SPOS][i%SPOS] = Wk[i]; wv_s[i/SPOS][i%SPOS] = Wv[i]; }
    if (tid < SPOS){ bk_s[tid] = bk[tid]; bv_s[tid] = bv[tid]; }
    __syncthreads();
    int b = blockIdx.x;
    int d = blockIdx.y * 128 + tid;
    float ch[SPOS];
    const float* cp = img + ((size_t)b * HID + d) * SPOS;
    #pragma unroll
    for (int s = 0; s < SPOS; s++) ch[s] = cp[s];
    for (int s = 0; s < SPOS; s++){
        float ak = bk_s[s], av = bv_s[s];
        #pragma unroll
        for (int sp = 0; sp < SPOS; sp++){ ak += ch[sp] * wk_s[s][sp]; av += ch[sp] * wv_s[s][sp]; }
        g_keys[b][s][d] = tanhf(ak);
        g_vals[b][s][d] = tanhf(av);
    }
}

__global__ void init_state(const float* __restrict__ pooled, const float* __restrict__ embed,
                           const int* __restrict__ sos){
    int idx = blockIdx.x * blockDim.x + threadIdx.x;
    if (idx >= BATCH * HID) return;
    int b = idx >> 9, j = idx & 511;
    float p = pooled[b * HID + j];
    g_c[(0*BATCH + b)*HID + j] = p;
    g_c[(1*BATCH + b)*HID + j] = p;
    int kp = j >> 1, par = j & 1;
    ((float*)&g_h0T[0][0])[(kp*32 + b)*2 + par] = p;
    ((float*)&g_h1T[0][0])[(kp*32 + b)*2 + par] = p;
    ((float*)&g_hcatT[0][0])[(kp*64 + b)*2 + par] = p;
    ((float*)&g_hcatT[0][0])[(kp*64 + 32 + b)*2 + par] = p;
    float e = embed[(size_t)(*sos) * HID + j];
    ((float*)&g_embT[0][0])[(kp*32 + b)*2 + par] = e;
}

// ---------------- host ----------------
static void* symaddr(const void* sym){
    void* p = nullptr;
    cudaGetSymbolAddress(&p, sym);
    return p;
}

extern "C" void kernel_launch(void* const* d_in, const int* in_sizes, int n_in,
                              void* d_out, int out_size){
    const float* img    = (const float*)d_in[0];
    const float* pooled = (const float*)d_in[1];
    const float* embed  = (const float*)d_in[2];
    const float* Wq     = (const float*)d_in[3];
    const float* bq     = (const float*)d_in[4];
    const float* Wk     = (const float*)d_in[5];
    const float* bk     = (const float*)d_in[6];
    const float* Wv     = (const float*)d_in[7];
    const float* bv     = (const float*)d_in[8];
    const float* Wih    = (const float*)d_in[9];
    const float* Whh    = (const float*)d_in[10];
    const float* bih    = (const float*)d_in[11];
    const float* bhh    = (const float*)d_in[12];
    const float* projW  = (const float*)d_in[13];
    const float* projb  = (const float*)d_in[14];
    const float* hattW  = (const float*)d_in[15];
    const float* hattb  = (const float*)d_in[16];
    const int*   sos    = (const int*)d_in[17];

    float2* Wih2   = (float2*)symaddr(g_Wih2);
    float2* Whh2   = (float2*)symaddr(g_Whh2);
    float2* Wq2    = (float2*)symaddr(g_Wq2);
    float2* hattW2 = (float2*)symaddr(g_hattW2);
    float2* projW2 = (float2*)symaddr(g_projW2);

    dim3 tb(32, 8);
    transpose_pair<<<dim3(16, 16),  tb>>>(Wq,    Wq2,    HID,  HID,   HID);
    transpose_pair<<<dim3(16, 32),  tb>>>(hattW, hattW2, HID,  2*HID, HID);
    transpose_pair<<<dim3(316, 16), tb>>>(projW, projW2, VOC,  HID,   VPAD);
    for (int l = 0; l < L2L; l++){
        transpose_pair<<<dim3(64, 16), tb>>>(Wih + (size_t)l*4*HID*HID, Wih2 + (size_t)l*(HID/2)*4*HID, 4*HID, HID, 4*HID);
        transpose_pair<<<dim3(64, 16), tb>>>(Whh + (size_t)l*4*HID*HID, Whh2 + (size_t)l*(HID/2)*4*HID, 4*HID, HID, 4*HID);
    }
    precompute_kv<<<dim3(BATCH, 4), 128>>>(img, Wk, bk, Wv, bv);
    init_state<<<64, 256>>>(pooled, embed, sos);

    decoder_persistent<<<NB, NT>>>(bq, bih, bhh, projb, hattb, embed, (float*)d_out);
}